// round 3
// baseline (speedup 1.0000x reference)
#include <cuda_runtime.h>

#define BSZ 32
#define SL  512
#define CL  20
#define D   256
#define NH  4
#define HD  64

typedef unsigned long long u64;

// ---------------- scratch (device globals; no allocation allowed) ----------
__device__ float g_X[BSZ*SL*D];                 // embedding + PE (residual)
__device__ float g_Q[BSZ*SL*D];
__device__ float g_K[BSZ*SL*D];
__device__ float g_V[BSZ*SL*D];
__device__ float g_O[BSZ*SL*D];                 // attention output (head concat)
__device__ float g_Z[BSZ*SL*D];                 // FC output
__device__ float g_N[BSZ*SL*D];                 // post-LN, zeroed beyond length

// ---------------- packed f32x2 helpers --------------------------------------
__device__ __forceinline__ u64 dupf(float x){u64 d;asm("mov.b64 %0,{%1,%1};":"=l"(d):"f"(x));return d;}
__device__ __forceinline__ u64 pack2(float lo,float hi){u64 d;asm("mov.b64 %0,{%1,%2};":"=l"(d):"f"(lo),"f"(hi));return d;}
__device__ __forceinline__ void unpack2(u64 d,float&lo,float&hi){asm("mov.b64 {%0,%1},%2;":"=f"(lo),"=f"(hi):"l"(d));}
__device__ __forceinline__ void fma2(u64&a,u64 x,u64 y){asm("fma.rn.f32x2 %0,%1,%2,%0;":"+l"(a):"l"(x),"l"(y));}
__device__ __forceinline__ u64 mul2(u64 x,u64 y){u64 r;asm("mul.rn.f32x2 %0,%1,%2;":"=l"(r):"l"(x),"l"(y));return r;}

// ---------------- K1: embedding sum + bias + positional encoding -----------
__global__ void k_embed(const int* __restrict__ seqs, const int* __restrict__ lengths,
                        const float* __restrict__ emb, const float* __restrict__ bias,
                        const float* __restrict__ pe) {
    int row = blockIdx.x;                 // b*SL + s
    int b = row >> 9, s = row & (SL-1);
    int d = threadIdx.x;
    __shared__ int idx[CL];
    __shared__ int spos;
    if (d < CL) idx[d] = seqs[row*CL + d];
    if (d == 0) spos = (s < lengths[b]) ? (s + 1) : 0;
    __syncthreads();
    float acc = bias[d];
    #pragma unroll
    for (int c = 0; c < CL; c++) acc += emb[idx[c]*D + d];
    acc += pe[spos*D + d];
    g_X[row*D + d] = acc;
}

// ---------------- NT GEMM tile 128x128, K contiguous both, lda=ldb=D --------
__device__ __forceinline__ void gemm_nt_128x128(const float* __restrict__ A,
        const float* __restrict__ B, float* __restrict__ Cg) {
    __shared__ __align__(16) float As[16][128+4];
    __shared__ __align__(16) float Bs[16][128+4];
    u64 acc[4][8] = {};
    int tid = threadIdx.x, tx = tid&15, ty = tid>>4;
    int r = tid>>1, kk = (tid&1)*8;
    for (int k0 = 0; k0 < D; k0 += 16) {
        float4 a0 = *(const float4*)(A + r*D + k0 + kk);
        float4 a1 = *(const float4*)(A + r*D + k0 + kk + 4);
        float4 b0 = *(const float4*)(B + r*D + k0 + kk);
        float4 b1 = *(const float4*)(B + r*D + k0 + kk + 4);
        As[kk+0][r]=a0.x; As[kk+1][r]=a0.y; As[kk+2][r]=a0.z; As[kk+3][r]=a0.w;
        As[kk+4][r]=a1.x; As[kk+5][r]=a1.y; As[kk+6][r]=a1.z; As[kk+7][r]=a1.w;
        Bs[kk+0][r]=b0.x; Bs[kk+1][r]=b0.y; Bs[kk+2][r]=b0.z; Bs[kk+3][r]=b0.w;
        Bs[kk+4][r]=b1.x; Bs[kk+5][r]=b1.y; Bs[kk+6][r]=b1.z; Bs[kk+7][r]=b1.w;
        __syncthreads();
        #pragma unroll
        for (int k = 0; k < 16; k++) {
            const u64* pA = (const u64*)&As[k][ty*8];
            u64 Ad[4] = {pA[0], pA[1], pA[2], pA[3]};
            float4 v0 = *(const float4*)&Bs[k][tx*8];
            float4 v1 = *(const float4*)&Bs[k][tx*8+4];
            u64 Bd[8] = {dupf(v0.x),dupf(v0.y),dupf(v0.z),dupf(v0.w),
                         dupf(v1.x),dupf(v1.y),dupf(v1.z),dupf(v1.w)};
            #pragma unroll
            for (int i = 0; i < 4; i++)
                #pragma unroll
                for (int j = 0; j < 8; j++)
                    fma2(acc[i][j], Ad[i], Bd[j]);
        }
        __syncthreads();
    }
    int m0 = ty*8, n0 = tx*8;
    #pragma unroll
    for (int p = 0; p < 4; p++) {
        float lo[8], hi[8];
        #pragma unroll
        for (int j = 0; j < 8; j++) unpack2(acc[p][j], lo[j], hi[j]);
        *(float4*)&Cg[(m0+2*p  )*D + n0    ] = make_float4(lo[0],lo[1],lo[2],lo[3]);
        *(float4*)&Cg[(m0+2*p  )*D + n0 + 4] = make_float4(lo[4],lo[5],lo[6],lo[7]);
        *(float4*)&Cg[(m0+2*p+1)*D + n0    ] = make_float4(hi[0],hi[1],hi[2],hi[3]);
        *(float4*)&Cg[(m0+2*p+1)*D + n0 + 4] = make_float4(hi[4],hi[5],hi[6],hi[7]);
    }
}

// ---------------- K2: Q/K/V projections -------------------------------------
__global__ void __launch_bounds__(256) k_qkv(const float* __restrict__ Wq,
        const float* __restrict__ Wk, const float* __restrict__ Wv) {
    const float* W = (blockIdx.z==0) ? Wq : (blockIdx.z==1) ? Wk : Wv;
    float* C       = (blockIdx.z==0) ? g_Q : (blockIdx.z==1) ? g_K : g_V;
    gemm_nt_128x128(g_X + blockIdx.y*128*D, W + blockIdx.x*128*D,
                    C + blockIdx.y*128*D + blockIdx.x*128);
}

// ---------------- K3: fused flash attention ---------------------------------
// Head h of Y is rows [h*128,(h+1)*128) viewed as [512,64] contiguous (ld=64).
#define QSTR 132
#define VSTR 68
// smem float offsets
#define OFF_Q 0
#define OFF_K (64*QSTR)
#define OFF_P (2*64*QSTR)
#define OFF_V (OFF_P + 128*QSTR)
#define FLASH_SMEM_FLOATS (OFF_V + 128*VSTR)
__global__ void __launch_bounds__(256, 1) k_flash(const int* __restrict__ masks) {
    extern __shared__ __align__(16) float sm[];
    float* Qs = sm + OFF_Q;         // [64 hd][QSTR]  (hd-major, 128 q contiguous)
    float* Ks = sm + OFF_K;         // [64 hd][QSTR]  (hd-major, 128 key contiguous)
    float* Ps = sm + OFF_P;         // [128 key][QSTR] (key-major, q contiguous)
    float* Vs = sm + OFF_V;         // [128 key][VSTR] (key-major, hd contiguous)
    int bh = blockIdx.y, b = bh>>2, h = bh&3;
    int q0 = blockIdx.x*128;
    const float* Qg = g_Q + b*SL*D + h*SL*HD + q0*HD;
    const float* Kg = g_K + b*SL*D + h*SL*HD;
    const float* Vg = g_V + b*SL*D + h*SL*HD;
    const int*   Mg = masks + b*SL*SL;
    int tid = threadIdx.x, tx = tid&15, ty = tid>>4;
    int r = tid>>1, c0 = (tid&1)*32;

    { // Q tile [128 q][64 hd] -> Qs transposed
        #pragma unroll
        for (int c = 0; c < 32; c += 4) {
            float4 v = *(const float4*)(Qg + r*HD + c0 + c);
            Qs[(c0+c+0)*QSTR+r]=v.x; Qs[(c0+c+1)*QSTR+r]=v.y;
            Qs[(c0+c+2)*QSTR+r]=v.z; Qs[(c0+c+3)*QSTR+r]=v.w;
        }
    }
    u64 accO[4][4] = {};
    float mrow[8], lrow[8];
    #pragma unroll
    for (int i = 0; i < 8; i++) { mrow[i] = -3.0e38f; lrow[i] = 0.0f; }

    for (int kt = 0; kt < 4; kt++) {
        int k0 = kt*128;
        __syncthreads();
        // K tile [128 key][64 hd] -> Ks transposed; V tile -> Vs direct
        #pragma unroll
        for (int c = 0; c < 32; c += 4) {
            float4 kv = *(const float4*)(Kg + (k0+r)*HD + c0 + c);
            Ks[(c0+c+0)*QSTR+r]=kv.x; Ks[(c0+c+1)*QSTR+r]=kv.y;
            Ks[(c0+c+2)*QSTR+r]=kv.z; Ks[(c0+c+3)*QSTR+r]=kv.w;
            float4 vv = *(const float4*)(Vg + (k0+r)*HD + c0 + c);
            *(float4*)&Vs[r*VSTR + c0 + c] = vv;
        }
        __syncthreads();
        // S = Q @ K^T tile [128 q][128 key], micro 8x8
        u64 accS[4][8] = {};
        #pragma unroll 16
        for (int k = 0; k < 64; k++) {
            const u64* pA = (const u64*)&Qs[k*QSTR + ty*8];
            u64 Ad[4] = {pA[0], pA[1], pA[2], pA[3]};
            float4 v0 = *(const float4*)&Ks[k*QSTR + tx*8];
            float4 v1 = *(const float4*)&Ks[k*QSTR + tx*8+4];
            u64 Bd[8] = {dupf(v0.x),dupf(v0.y),dupf(v0.z),dupf(v0.w),
                         dupf(v1.x),dupf(v1.y),dupf(v1.z),dupf(v1.w)};
            #pragma unroll
            for (int i = 0; i < 4; i++)
                #pragma unroll
                for (int j = 0; j < 8; j++)
                    fma2(accS[i][j], Ad[i], Bd[j]);
        }
        // online softmax per row-pair
        #pragma unroll
        for (int p = 0; p < 4; p++) {
            float s0[8], s1[8];
            #pragma unroll
            for (int j = 0; j < 8; j++) unpack2(accS[p][j], s0[j], s1[j]);
            int r0 = q0 + ty*8 + 2*p;
            int4 ma0 = *(const int4*)(Mg + r0*SL + k0 + tx*8);
            int4 ma1 = *(const int4*)(Mg + r0*SL + k0 + tx*8 + 4);
            int4 mb0 = *(const int4*)(Mg + (r0+1)*SL + k0 + tx*8);
            int4 mb1 = *(const int4*)(Mg + (r0+1)*SL + k0 + tx*8 + 4);
            int mk0[8] = {ma0.x,ma0.y,ma0.z,ma0.w, ma1.x,ma1.y,ma1.z,ma1.w};
            int mk1[8] = {mb0.x,mb0.y,mb0.z,mb0.w, mb1.x,mb1.y,mb1.z,mb1.w};
            #pragma unroll
            for (int j = 0; j < 8; j++) {
                s0[j] = mk0[j] ? s0[j]*0.125f : -1e30f;
                s1[j] = mk1[j] ? s1[j]*0.125f : -1e30f;
            }
            float mx0 = s0[0], mx1 = s1[0];
            #pragma unroll
            for (int j = 1; j < 8; j++) { mx0 = fmaxf(mx0, s0[j]); mx1 = fmaxf(mx1, s1[j]); }
            #pragma unroll
            for (int o = 8; o > 0; o >>= 1) {
                mx0 = fmaxf(mx0, __shfl_xor_sync(0xffffffffu, mx0, o, 16));
                mx1 = fmaxf(mx1, __shfl_xor_sync(0xffffffffu, mx1, o, 16));
            }
            float nm0 = fmaxf(mrow[2*p],   mx0);
            float nm1 = fmaxf(mrow[2*p+1], mx1);
            float cf0 = __expf(mrow[2*p]   - nm0);
            float cf1 = __expf(mrow[2*p+1] - nm1);
            mrow[2*p] = nm0; mrow[2*p+1] = nm1;
            float rs0 = 0.f, rs1 = 0.f;
            #pragma unroll
            for (int j = 0; j < 8; j++) {
                s0[j] = __expf(s0[j] - nm0); rs0 += s0[j];
                s1[j] = __expf(s1[j] - nm1); rs1 += s1[j];
            }
            #pragma unroll
            for (int o = 8; o > 0; o >>= 1) {
                rs0 += __shfl_xor_sync(0xffffffffu, rs0, o, 16);
                rs1 += __shfl_xor_sync(0xffffffffu, rs1, o, 16);
            }
            lrow[2*p]   = lrow[2*p]  *cf0 + rs0;
            lrow[2*p+1] = lrow[2*p+1]*cf1 + rs1;
            u64 cp = pack2(cf0, cf1);
            #pragma unroll
            for (int j = 0; j < 4; j++) accO[p][j] = mul2(accO[p][j], cp);
            #pragma unroll
            for (int j = 0; j < 8; j++)
                *(u64*)&Ps[(tx*8+j)*QSTR + ty*8 + 2*p] = pack2(s0[j], s1[j]);
        }
        __syncthreads();
        // O += P @ V  ([128 q][64 hd]), micro 8x4
        #pragma unroll 16
        for (int k = 0; k < 128; k++) {
            const u64* pA = (const u64*)&Ps[k*QSTR + ty*8];
            u64 Ad[4] = {pA[0], pA[1], pA[2], pA[3]};
            float4 bv = *(const float4*)&Vs[k*VSTR + tx*4];
            u64 Bd[4] = {dupf(bv.x),dupf(bv.y),dupf(bv.z),dupf(bv.w)};
            #pragma unroll
            for (int i = 0; i < 4; i++)
                #pragma unroll
                for (int j = 0; j < 4; j++)
                    fma2(accO[i][j], Ad[i], Bd[j]);
        }
    }
    // finalize: O /= l, write head-concat layout
    #pragma unroll
    for (int p = 0; p < 4; p++) {
        u64 il = pack2(1.0f/lrow[2*p], 1.0f/lrow[2*p+1]);
        u64 t0 = mul2(accO[p][0], il), t1 = mul2(accO[p][1], il);
        u64 t2 = mul2(accO[p][2], il), t3 = mul2(accO[p][3], il);
        float l0,h0,l1,h1,l2,h2,l3,h3;
        unpack2(t0,l0,h0); unpack2(t1,l1,h1); unpack2(t2,l2,h2); unpack2(t3,l3,h3);
        int row = b*SL + q0 + ty*8 + 2*p;
        int col = h*HD + tx*4;
        *(float4*)&g_O[row*D + col]     = make_float4(l0,l1,l2,l3);
        *(float4*)&g_O[(row+1)*D + col] = make_float4(h0,h1,h2,h3);
    }
}

// ---------------- K4: Z = O @ Wfc^T ------------------------------------------
__global__ void __launch_bounds__(256) k_fc(const float* __restrict__ Wfc) {
    gemm_nt_128x128(g_O + blockIdx.y*128*D, Wfc + blockIdx.x*128*D,
                    g_Z + blockIdx.y*128*D + blockIdx.x*128);
}

// ---------------- K5: residual + LayerNorm + zero invalid --------------------
__global__ void k_ln(const int* __restrict__ lengths, const float* __restrict__ gw,
                     const float* __restrict__ gb) {
    int row = blockIdx.x; int b = row >> 9, s = row & (SL-1);
    int d = threadIdx.x;
    float v = g_Z[row*D + d] + g_X[row*D + d];
    __shared__ float red[256];
    red[d] = v; __syncthreads();
    for (int o = 128; o > 0; o >>= 1) { if (d < o) red[d] += red[d+o]; __syncthreads(); }
    float mu = red[0] * (1.0f/D); __syncthreads();
    float cv = v - mu;
    red[d] = cv*cv; __syncthreads();
    for (int o = 128; o > 0; o >>= 1) { if (d < o) red[d] += red[d+o]; __syncthreads(); }
    float var = red[0] * (1.0f/D);
    float o = cv * rsqrtf(var + 1e-5f) * gw[d] + gb[d];
    g_N[row*D + d] = (s < lengths[b]) ? o : 0.0f;
}

// ---------------- K6: triangular pooling + output linear ---------------------
__global__ void k_pool(const int* __restrict__ lengths, const float* __restrict__ ow,
                       const float* __restrict__ ob, float* __restrict__ out) {
    int b = blockIdx.x, d = threadIdx.x;
    int len = lengths[b];
    float inv4 = 4.0f / (float)len;
    float u0=0.f, u1=0.f, u2=0.f, u3=0.f;
    const float* xp = g_N + b*SL*D + d;
    for (int s = 0; s < len; s++) {       // x is exactly 0 beyond len
        float x = xp[s*D];
        float sv = inv4 * (float)(s + 1);
        float w0 = 1.0f - fabsf(sv - 1.0f)*0.25f;
        float w1 = 1.0f - fabsf(sv - 2.0f)*0.25f;
        float w2 = 1.0f - fabsf(sv - 3.0f)*0.25f;
        float w3 = 1.0f - fabsf(sv - 4.0f)*0.25f;
        u0 += w0*w0*x; u1 += w1*w1*x; u2 += w2*w2*x; u3 += w3*w3*x;
    }
    float p0 = u0*ow[d] + u1*ow[256+d] + u2*ow[512+d] + u3*ow[768+d];
    float p1 = u0*ow[1024+d] + u1*ow[1280+d] + u2*ow[1536+d] + u3*ow[1792+d];
    __shared__ float r0[256], r1[256];
    r0[d] = p0; r1[d] = p1; __syncthreads();
    for (int o = 128; o > 0; o >>= 1) {
        if (d < o) { r0[d] += r0[d+o]; r1[d] += r1[d+o]; }
        __syncthreads();
    }
    if (d == 0) { out[b*2+0] = r0[0] + ob[0]; out[b*2+1] = r1[0] + ob[1]; }
}

// ---------------- launch -----------------------------------------------------
extern "C" void kernel_launch(void* const* d_in, const int* in_sizes, int n_in,
                              void* d_out, int out_size) {
    const int*   seqs    = (const int*)  d_in[0];
    const int*   masks   = (const int*)  d_in[1];
    const int*   lengths = (const int*)  d_in[2];
    const float* emb     = (const float*)d_in[5];
    const float* bias    = (const float*)d_in[6];
    const float* pe      = (const float*)d_in[7];
    const float* Wq      = (const float*)d_in[8];
    const float* Wk      = (const float*)d_in[9];
    const float* Wv      = (const float*)d_in[10];
    const float* Wfc     = (const float*)d_in[11];
    const float* lng     = (const float*)d_in[12];
    const float* lnb     = (const float*)d_in[13];
    const float* ow      = (const float*)d_in[14];
    const float* ob      = (const float*)d_in[15];
    float* out = (float*)d_out;

    const int flash_smem = FLASH_SMEM_FLOATS * 4;   // 169984 bytes
    cudaFuncSetAttribute(k_flash, cudaFuncAttributeMaxDynamicSharedMemorySize, flash_smem);

    k_embed<<<BSZ*SL, 256>>>(seqs, lengths, emb, bias, pe);
    k_qkv  <<<dim3(D/128, BSZ*SL/128, 3), 256>>>(Wq, Wk, Wv);
    k_flash<<<dim3(SL/128, BSZ*NH), 256, flash_smem>>>(masks);
    k_fc   <<<dim3(D/128, BSZ*SL/128, 1), 256>>>(Wfc);
    k_ln   <<<BSZ*SL, 256>>>(lengths, lng, lnb);
    k_pool <<<BSZ, 256>>>(lengths, ow, ob, out);
}